// round 15
// baseline (speedup 1.0000x reference)
#include <cuda_runtime.h>
#include <cuda.h>
#include <cuda_bf16.h>
#include <math.h>
#include <stdint.h>

#define NB 8
#define T  2048
#define E  1024
#define MT (NB*T)

typedef __nv_bfloat16 bf16;

// ------------------------- scratch (device globals) -------------------------
__device__ bf16 g_Xbh[(size_t)MT*E], g_Xbl[(size_t)MT*E];
__device__ float g_X32[(size_t)MT*E];            // tf32-rna-rounded X
__device__ bf16 g_Wqh[(size_t)E*E], g_Wql[(size_t)E*E];
__device__ bf16 g_Wkh[(size_t)E*E], g_Wkl[(size_t)E*E];
__device__ float g_Wv32[(size_t)E*E];            // tf32-rna-rounded Wv
__device__ bf16 g_Qbh[(size_t)MT*E], g_Qbl[(size_t)MT*E];
__device__ bf16 g_Kbh[(size_t)MT*E], g_Kbl[(size_t)MT*E];
__device__ float g_Vth[(size_t)NB*E*T];          // [b][f][t], tf32-rounded, later *= linv
__device__ float g_S [(size_t)NB*T*T];
__device__ float g_Ph[(size_t)NB*T*T];           // rna(exp(S - m_j)), unnormalized
__device__ float g_Li[NB*T];

// ------------------------- helpers -------------------------
__device__ __forceinline__ uint32_t smem_u32(const void* p) {
    uint32_t a;
    asm("{ .reg .u64 t; cvta.to.shared.u64 t, %1; cvt.u32.u64 %0, t; }" : "=r"(a) : "l"(p));
    return a;
}
__device__ __forceinline__ float tf32_rna(float x) {
    uint32_t u; asm("cvt.rna.tf32.f32 %0, %1;" : "=r"(u) : "f"(x));
    return __uint_as_float(u);
}
__device__ __forceinline__ void tma2d(uint32_t dst, const void* map, int x, int y, uint32_t mbar) {
    asm volatile("cp.async.bulk.tensor.2d.shared::cta.global.tile.mbarrier::complete_tx::bytes "
                 "[%0], [%1, {%2, %3}], [%4];"
                 :: "r"(dst), "l"(map), "r"(x), "r"(y), "r"(mbar) : "memory");
}
#define MBAR_INIT(a, c) \
    asm volatile("mbarrier.init.shared.b64 [%0], %1;" :: "r"((uint32_t)(a)), "r"((uint32_t)(c)) : "memory")
#define MBAR_EXPECT(a, b) \
    asm volatile("mbarrier.arrive.expect_tx.shared.b64 _, [%0], %1;" :: "r"((uint32_t)(a)), "r"((uint32_t)(b)) : "memory")
#define MBAR_ARRIVE(a) \
    asm volatile("mbarrier.arrive.shared.b64 _, [%0];" :: "r"((uint32_t)(a)) : "memory")
#define MBAR_WAIT(a, ph) do { \
    uint32_t _m = (uint32_t)(a), _p = (uint32_t)(ph), _d; \
    asm volatile("{\n\t.reg .pred p;\n\t" \
        "mbarrier.try_wait.parity.acquire.cta.shared::cta.b64 p, [%1], %2;\n\t" \
        "selp.b32 %0,1,0,p;\n\t}" : "=r"(_d) : "r"(_m), "r"(_p) : "memory"); \
    if (!_d) { \
        asm volatile("{\n\t.reg .pred P1;\n\t" \
            "WL_%=:\n\t" \
            "mbarrier.try_wait.parity.acquire.cta.shared::cta.b64 P1, [%0], %1, 0x989680;\n\t" \
            "@P1 bra.uni WD_%=;\n\tbra.uni WL_%=;\n\tWD_%=:\n\t}" \
            :: "r"(_m), "r"(_p) : "memory"); \
    } \
} while(0)
__device__ __forceinline__ void ldsm4(uint32_t& r0, uint32_t& r1, uint32_t& r2, uint32_t& r3,
                                      uint32_t addr) {
    asm volatile("ldmatrix.sync.aligned.m8n8.x4.shared.b16 {%0,%1,%2,%3}, [%4];"
                 : "=r"(r0), "=r"(r1), "=r"(r2), "=r"(r3) : "r"(addr));
}
__device__ __forceinline__ void mma16(float* d, uint32_t a0, uint32_t a1, uint32_t a2, uint32_t a3,
                                      uint32_t b0, uint32_t b1) {
    asm("mma.sync.aligned.m16n8k16.row.col.f32.bf16.bf16.f32 "
        "{%0,%1,%2,%3},{%4,%5,%6,%7},{%8,%9},{%0,%1,%2,%3};"
        : "+f"(d[0]), "+f"(d[1]), "+f"(d[2]), "+f"(d[3])
        : "r"(a0), "r"(a1), "r"(a2), "r"(a3), "r"(b0), "r"(b1));
}
__device__ __forceinline__ void mma8(float* d, uint32_t a0, uint32_t a1, uint32_t a2, uint32_t a3,
                                     uint32_t b0, uint32_t b1) {
    asm("mma.sync.aligned.m16n8k8.row.col.f32.tf32.tf32.f32 "
        "{%0,%1,%2,%3},{%4,%5,%6,%7},{%8,%9},{%0,%1,%2,%3};"
        : "+f"(d[0]), "+f"(d[1]), "+f"(d[2]), "+f"(d[3])
        : "r"(a0), "r"(a1), "r"(a2), "r"(a3), "r"(b0), "r"(b1));
}
__device__ __forceinline__ uint32_t pack_bf2(float x, float y) {
    bf16 hx = __float2bfloat16(x), hy = __float2bfloat16(y);
    uint16_t ux = *(uint16_t*)&hx, uy = *(uint16_t*)&hy;
    uint32_t r;
    asm("mov.b32 %0, {%1, %2};" : "=r"(r) : "h"(ux), "h"(uy));
    return r;
}

// ============================================================
// bf16x2 3-pass GEMM, TMA + ldmatrix, warp-specialized producer.
// 544 threads: warps 0-15 compute (4x4, 64x32 each), warp 16 = TMA producer.
// Tile 256x128, BK=64, 2 stages x 96KB.
// MODE 0: merged Q+K proj (blockIdx.z selects weights/bias/outputs)
// MODE 2: scores (blockIdx.z = batch; triangle grid; fp32 store to S)
// ============================================================
#define BSTG 98304
#define BSMEM_BYTES (2*BSTG)

template<int MODE>
__global__ void __launch_bounds__(544, 1) gemm_bf16(
    const __grid_constant__ CUtensorMap mAh, const __grid_constant__ CUtensorMap mAl,
    const __grid_constant__ CUtensorMap mBh, const __grid_constant__ CUtensorMap mBl,
    const __grid_constant__ CUtensorMap mB2h, const __grid_constant__ CUtensorMap mB2l,
    float* __restrict__ outf,
    bf16* __restrict__ oh0, bf16* __restrict__ ol0,
    bf16* __restrict__ oh1, bf16* __restrict__ ol1,
    const float* __restrict__ bias0, const float* __restrict__ bias1)
{
    const int m0 = blockIdx.y * 256, n0 = blockIdx.x * 128;
    if (MODE == 2 && n0 >= m0 + 256) return;

    extern __shared__ __align__(1024) char smem[];
    __shared__ __align__(8) uint64_t fullb[2], emptyb[2];
    const uint32_t sb = smem_u32(smem);
    const int tid = threadIdx.x;
    const int lane = tid & 31, warp = tid >> 5;
    const int wm = warp >> 2, wn = warp & 3;
    const int g = lane >> 2, c = lane & 3;
    const int z = blockIdx.z;

    const int rowA = (MODE == 2) ? z*T + m0 : m0;
    const int rowB = (MODE == 2) ? z*T + n0 : n0;
    const int nch = E/64;

    const CUtensorMap* pBh = (MODE == 0 && z) ? &mB2h : &mBh;
    const CUtensorMap* pBl = (MODE == 0 && z) ? &mB2l : &mBl;

    if (tid == 0) {
        MBAR_INIT(smem_u32(&fullb[0]), 1);  MBAR_INIT(smem_u32(&fullb[1]), 1);
        MBAR_INIT(smem_u32(&emptyb[0]), 16); MBAR_INIT(smem_u32(&emptyb[1]), 16);
    }
    __syncthreads();

    if (warp == 16) {
        if (lane == 0) {
            for (int ck = 0; ck < nch; ck++) {
                const int st = ck & 1;
                MBAR_WAIT(smem_u32(&emptyb[st]), 1 ^ ((ck >> 1) & 1));
                uint32_t base = sb + st*BSTG;
                uint32_t fb = smem_u32(&fullb[st]);
                MBAR_EXPECT(fb, BSTG);
                tma2d(base + 0,     &mAh, 64*ck, rowA, fb);
                tma2d(base + 32768, &mAl, 64*ck, rowA, fb);
                tma2d(base + 65536, pBh, 64*ck, rowB, fb);
                tma2d(base + 81920, pBl, 64*ck, rowB, fb);
            }
        }
        return;
    }

    float acc[4][4][4];
    #pragma unroll
    for (int mi = 0; mi < 4; mi++)
        #pragma unroll
        for (int ni = 0; ni < 4; ni++)
            #pragma unroll
            for (int q = 0; q < 4; q++) acc[mi][ni][q] = 0.f;

    const int lmat = lane >> 3, lrow = lane & 7;
    const int aBit = lmat >> 1, bBit = lmat & 1;
    uint32_t aRow[4], bRow[2];
    #pragma unroll
    for (int mi = 0; mi < 4; mi++)
        aRow[mi] = (uint32_t)((wm*64 + mi*16 + ((lmat & 1) << 3) + lrow) * 128);
    #pragma unroll
    for (int p = 0; p < 2; p++)
        bRow[p] = (uint32_t)((wn*32 + p*16 + ((lmat >> 1) << 3) + lrow) * 128);

    for (int ck = 0; ck < nch; ck++) {
        const int st = ck & 1;
        MBAR_WAIT(smem_u32(&fullb[st]), (ck >> 1) & 1);

        const uint32_t stb = sb + st*BSTG;
        const uint32_t Ah = stb, Al = stb + 32768, Bh = stb + 65536, Bl = stb + 81920;

        #pragma unroll
        for (int ks = 0; ks < 4; ks++) {
            const uint32_t aU = (uint32_t)(((2*ks + aBit) ^ lrow) << 4);
            const uint32_t bU = (uint32_t)(((2*ks + bBit) ^ lrow) << 4);
            uint32_t bh[4][2], bl[4][2];
            ldsm4(bh[0][0], bh[0][1], bh[1][0], bh[1][1], Bh + bRow[0] + bU);
            ldsm4(bh[2][0], bh[2][1], bh[3][0], bh[3][1], Bh + bRow[1] + bU);
            ldsm4(bl[0][0], bl[0][1], bl[1][0], bl[1][1], Bl + bRow[0] + bU);
            ldsm4(bl[2][0], bl[2][1], bl[3][0], bl[3][1], Bl + bRow[1] + bU);
            uint32_t af[4][4];
            #pragma unroll
            for (int mi = 0; mi < 4; mi++)
                ldsm4(af[mi][0], af[mi][1], af[mi][2], af[mi][3], Ah + aRow[mi] + aU);
            #pragma unroll
            for (int mi = 0; mi < 4; mi++)
                #pragma unroll
                for (int ni = 0; ni < 4; ni++)
                    mma16(acc[mi][ni], af[mi][0], af[mi][1], af[mi][2], af[mi][3],
                          bh[ni][0], bh[ni][1]);
            #pragma unroll
            for (int mi = 0; mi < 4; mi++)
                #pragma unroll
                for (int ni = 0; ni < 4; ni++)
                    mma16(acc[mi][ni], af[mi][0], af[mi][1], af[mi][2], af[mi][3],
                          bl[ni][0], bl[ni][1]);
            #pragma unroll
            for (int mi = 0; mi < 4; mi++)
                ldsm4(af[mi][0], af[mi][1], af[mi][2], af[mi][3], Al + aRow[mi] + aU);
            #pragma unroll
            for (int mi = 0; mi < 4; mi++)
                #pragma unroll
                for (int ni = 0; ni < 4; ni++)
                    mma16(acc[mi][ni], af[mi][0], af[mi][1], af[mi][2], af[mi][3],
                          bh[ni][0], bh[ni][1]);
        }
        if (lane == 0) MBAR_ARRIVE(smem_u32(&emptyb[st]));
    }

    bf16* oh = (MODE == 0 && z) ? oh1 : oh0;
    bf16* ol = (MODE == 0 && z) ? ol1 : ol0;
    const float* bias = (MODE == 0 && z) ? bias1 : bias0;

    #pragma unroll
    for (int mi = 0; mi < 4; mi++) {
        #pragma unroll
        for (int ni = 0; ni < 4; ni++) {
            const int r1 = m0 + wm*64 + mi*16 + g, r2 = r1 + 8;
            const int col = n0 + wn*32 + ni*8 + 2*c;
            float* a = acc[mi][ni];
            if (MODE == 0) {
                float2 bs = *(const float2*)(bias + col);
                float y0 = a[0] + bs.x, y1 = a[1] + bs.y;
                float y2 = a[2] + bs.x, y3 = a[3] + bs.y;
                float h0 = __bfloat162float(__float2bfloat16(y0));
                float h1 = __bfloat162float(__float2bfloat16(y1));
                float h2 = __bfloat162float(__float2bfloat16(y2));
                float h3 = __bfloat162float(__float2bfloat16(y3));
                *(uint32_t*)(oh + (size_t)r1*E + col) = pack_bf2(y0, y1);
                *(uint32_t*)(ol + (size_t)r1*E + col) = pack_bf2(y0 - h0, y1 - h1);
                *(uint32_t*)(oh + (size_t)r2*E + col) = pack_bf2(y2, y3);
                *(uint32_t*)(ol + (size_t)r2*E + col) = pack_bf2(y2 - h2, y3 - h3);
            } else {
                float* Sb = outf + (size_t)z*T*T;
                *(float2*)(Sb + (size_t)r1*T + col) = make_float2(a[0], a[1]);
                *(float2*)(Sb + (size_t)r2*T + col) = make_float2(a[2], a[3]);
            }
        }
    }
}

// ============================================================
// tf32 1-pass GEMM, TMA + ldmatrix + producer warp. 256x128, BK=32, 4 stages.
// VMODE 0: out  (A=expS, B=Vt*linv, k stops past diagonal; longest-first y)
// VMODE 1: Vproj (A=X32 tf32-rna, B=Wv32 tf32-rna — MMA exact;
//                 +bias, tf32-rounded TRANSPOSED store -> Vt[b][f][t])
// ============================================================
#define OSTG 49152
#define OSMEM_BYTES (4*OSTG)

template<int VMODE>
__global__ void __launch_bounds__(544, 1) gemm_tf32(
    const __grid_constant__ CUtensorMap mA, const __grid_constant__ CUtensorMap mB,
    float* __restrict__ out0, const float* __restrict__ bias)
{
    const int yb = (VMODE == 0) ? (gridDim.y - 1 - blockIdx.y) : blockIdx.y;
    const int m0 = yb * 256, n0 = blockIdx.x * 128;
    extern __shared__ __align__(1024) char smem[];
    __shared__ __align__(8) uint64_t fullb[4], emptyb[4];
    const uint32_t sb = smem_u32(smem);
    const int tid = threadIdx.x;
    const int lane = tid & 31, warp = tid >> 5;
    const int wm = warp >> 2, wn = warp & 3;
    const int g = lane >> 2, c = lane & 3;
    const int b = blockIdx.z;

    const int rowA = (VMODE == 0) ? b*T + m0 : m0;
    const int rowB = (VMODE == 0) ? b*E + n0 : n0;
    const int nch = (VMODE == 0) ? m0/32 + 8 : E/32;

    if (tid == 0) {
        #pragma unroll
        for (int s = 0; s < 4; s++) {
            MBAR_INIT(smem_u32(&fullb[s]), 1);
            MBAR_INIT(smem_u32(&emptyb[s]), 16);
        }
    }
    __syncthreads();

    if (warp == 16) {
        if (lane == 0) {
            for (int ck = 0; ck < nch; ck++) {
                const int st = ck & 3;
                MBAR_WAIT(smem_u32(&emptyb[st]), 1 ^ ((ck >> 2) & 1));
                uint32_t base = sb + st*OSTG;
                uint32_t fb = smem_u32(&fullb[st]);
                MBAR_EXPECT(fb, OSTG);
                tma2d(base + 0,     &mA, 32*ck, rowA, fb);
                tma2d(base + 32768, &mB, 32*ck, rowB, fb);
            }
        }
        return;
    }

    float acc[4][4][4];
    #pragma unroll
    for (int mi = 0; mi < 4; mi++)
        #pragma unroll
        for (int ni = 0; ni < 4; ni++)
            #pragma unroll
            for (int q = 0; q < 4; q++) acc[mi][ni][q] = 0.f;

    const int lmat = lane >> 3, lrow = lane & 7;
    const int aBit = lmat >> 1, bBit = lmat & 1;
    uint32_t aRow[4], bRow[2];
    #pragma unroll
    for (int mi = 0; mi < 4; mi++)
        aRow[mi] = (uint32_t)((wm*64 + mi*16 + ((lmat & 1) << 3) + lrow) * 128);
    #pragma unroll
    for (int p = 0; p < 2; p++)
        bRow[p] = (uint32_t)((wn*32 + p*16 + ((lmat >> 1) << 3) + lrow) * 128);

    for (int ck = 0; ck < nch; ck++) {
        const int st = ck & 3;
        MBAR_WAIT(smem_u32(&fullb[st]), (ck >> 2) & 1);

        const uint32_t stb = sb + st*OSTG;
        const uint32_t Aa = stb, Bb = stb + 32768;

        #pragma unroll
        for (int ks = 0; ks < 4; ks++) {
            const uint32_t aU = (uint32_t)(((2*ks + aBit) ^ lrow) << 4);
            const uint32_t bU = (uint32_t)(((2*ks + bBit) ^ lrow) << 4);
            uint32_t bh[4][2];
            ldsm4(bh[0][0], bh[0][1], bh[1][0], bh[1][1], Bb + bRow[0] + bU);
            ldsm4(bh[2][0], bh[2][1], bh[3][0], bh[3][1], Bb + bRow[1] + bU);
            #pragma unroll
            for (int mi = 0; mi < 4; mi++) {
                uint32_t a0, a1, a2, a3;
                ldsm4(a0, a1, a2, a3, Aa + aRow[mi] + aU);
                #pragma unroll
                for (int ni = 0; ni < 4; ni++)
                    mma8(acc[mi][ni], a0, a1, a2, a3, bh[ni][0], bh[ni][1]);
            }
        }
        if (lane == 0) MBAR_ARRIVE(smem_u32(&emptyb[st]));
    }

    #pragma unroll
    for (int mi = 0; mi < 4; mi++) {
        #pragma unroll
        for (int ni = 0; ni < 4; ni++) {
            const int r1 = m0 + wm*64 + mi*16 + g, r2 = r1 + 8;
            const int col = n0 + wn*32 + ni*8 + 2*c;
            float* a = acc[mi][ni];
            if (VMODE == 0) {
                float* Ob = out0 + (size_t)b*T*E;
                *(float2*)(Ob + (size_t)r1*E + col) = make_float2(a[0], a[1]);
                *(float2*)(Ob + (size_t)r2*E + col) = make_float2(a[2], a[3]);
            } else {
                float2 bs = *(const float2*)(bias + col);
                const size_t bo = (size_t)(m0 / T) * E * T;
                const int tl1 = (m0 % T) + wm*64 + mi*16 + g, tl2 = tl1 + 8;
                out0[bo + (size_t)col*T     + tl1] = tf32_rna(a[0] + bs.x);
                out0[bo + (size_t)(col+1)*T + tl1] = tf32_rna(a[1] + bs.y);
                out0[bo + (size_t)col*T     + tl2] = tf32_rna(a[2] + bs.x);
                out0[bo + (size_t)(col+1)*T + tl2] = tf32_rna(a[3] + bs.y);
            }
        }
    }
}

// ------------------------- elementwise kernels -------------------------
__global__ void __launch_bounds__(256) splitk_bf(
    const float* __restrict__ src, bf16* __restrict__ dh, bf16* __restrict__ dl,
    float* __restrict__ d32, int n4)
{
    int i = blockIdx.x * 256 + threadIdx.x;
    if (i >= n4) return;
    float4 v = ((const float4*)src)[i];
    uint32_t h0 = pack_bf2(v.x, v.y), h1 = pack_bf2(v.z, v.w);
    float r0 = v.x - __bfloat162float(__float2bfloat16(v.x));
    float r1 = v.y - __bfloat162float(__float2bfloat16(v.y));
    float r2 = v.z - __bfloat162float(__float2bfloat16(v.z));
    float r3 = v.w - __bfloat162float(__float2bfloat16(v.w));
    uint32_t l0 = pack_bf2(r0, r1), l1 = pack_bf2(r2, r3);
    ((uint2*)dh)[i] = make_uint2(h0, h1);
    ((uint2*)dl)[i] = make_uint2(l0, l1);
    if (d32) {
        float4 t;
        t.x = tf32_rna(v.x); t.y = tf32_rna(v.y);
        t.z = tf32_rna(v.z); t.w = tf32_rna(v.w);
        ((float4*)d32)[i] = t;
    }
}

__global__ void __launch_bounds__(256) roundtf(
    const float* __restrict__ src, float* __restrict__ dst, int n4)
{
    int i = blockIdx.x * 256 + threadIdx.x;
    if (i >= n4) return;
    float4 v = ((const float4*)src)[i];
    float4 t;
    t.x = tf32_rna(v.x); t.y = tf32_rna(v.y);
    t.z = tf32_rna(v.z); t.w = tf32_rna(v.w);
    ((float4*)dst)[i] = t;
}

// Fused column softmax: sweep1 = column max (i>=j, no exp);
// sweep2 = e=exp(s-m) ONCE, store rna(e) into P (with zero padding rows),
// accumulate column sum, write g_Li = 1/L. Strips of 32 cols, longest first.
__global__ void __launch_bounds__(256) softcol()
{
    const int bb = blockIdx.y;
    const int strip = gridDim.x - 1 - blockIdx.x;   // longest (j0=0) first
    const int j0 = strip * 32;
    const int c = threadIdx.x & 31, r = threadIdx.x >> 5;
    const int j = j0 + c;
    const float* S = g_S + (size_t)bb*T*T;
    float* P = g_Ph + (size_t)bb*T*T;

    // ---- sweep 1: column max over i >= j ----
    float m0v = -INFINITY, m1v = -INFINITY, m2v = -INFINITY, m3v = -INFINITY;
    #define MX(MM, II) do { int _i = (II); if (_i < T && _i >= j) \
        MM = fmaxf(MM, S[(size_t)_i*T + j]); } while(0)
    for (int i = j0 + r; i < T; i += 32) {
        MX(m0v, i); MX(m1v, i + 8); MX(m2v, i + 16); MX(m3v, i + 24);
    }
    #undef MX
    float M = fmaxf(fmaxf(m0v, m1v), fmaxf(m2v, m3v));
    __shared__ float sm_[8][33], sl_[8][33];
    sm_[r][c] = M;
    __syncthreads();
    if (r == 0) {
        #pragma unroll
        for (int rr = 1; rr < 8; rr++) M = fmaxf(M, sm_[rr][c]);
        sm_[0][c] = M;
    }
    __syncthreads();
    M = sm_[0][c];

    // ---- sweep 2: e = exp(s - M) once; store rna(e); sum ----
    float s0 = 0.f, s1 = 0.f, s2 = 0.f, s3 = 0.f;
    const int lo = (j0 >= 256) ? (j0 - 256) : 0;    // cover zero-padding rows
    #define EX(SS, II) do { int _i = (II); if (_i < T) { \
        float w = 0.f; \
        if (_i >= j) { float e = __expf(S[(size_t)_i*T + j] - M); SS += e; w = tf32_rna(e); } \
        P[(size_t)_i*T + j] = w; } } while(0)
    for (int i = lo + r; i < T; i += 32) {
        EX(s0, i); EX(s1, i + 8); EX(s2, i + 16); EX(s3, i + 24);
    }
    #undef EX
    float L = (s0 + s1) + (s2 + s3);
    sl_[r][c] = L;
    __syncthreads();
    if (r == 0) {
        #pragma unroll
        for (int rr = 1; rr < 8; rr++) L += sl_[rr][c];
        g_Li[bb*T + j] = 1.f / L;
    }
}

// Vt[b][f][t] *= Li[b][t], rna-rounded (folds softmax normalization into V)
__global__ void __launch_bounds__(256) vscale(int n4)
{
    int i = blockIdx.x * 256 + threadIdx.x;
    if (i >= n4) return;
    const int t0 = (i * 4) & (T - 1);
    const int row = (i * 4) / T;           // row = b*E + f
    const int b = row / E;
    float4 v = ((const float4*)g_Vth)[i];
    float4 li = *(const float4*)(g_Li + b*T + t0);
    v.x = tf32_rna(v.x * li.x);
    v.y = tf32_rna(v.y * li.y);
    v.z = tf32_rna(v.z * li.z);
    v.w = tf32_rna(v.w * li.w);
    ((float4*)g_Vth)[i] = v;
}

// ------------------------- host -------------------------
typedef CUresult (*PFN_encode)(CUtensorMap*, CUtensorMapDataType, cuuint32_t, void*,
    const cuuint64_t*, const cuuint64_t*, const cuuint32_t*, const cuuint32_t*,
    CUtensorMapInterleave, CUtensorMapSwizzle, CUtensorMapL2promotion, CUtensorMapFloatOOBfill);

static void mk2d(PFN_encode enc, CUtensorMap* tm, void* p, CUtensorMapDataType dt,
                 uint64_t w, uint64_t h, uint32_t bw, uint32_t bh, uint32_t esize) {
    cuuint64_t dims[2]    = {w, h};
    cuuint64_t strides[1] = {w * esize};
    cuuint32_t box[2]     = {bw, bh};
    cuuint32_t es[2]      = {1, 1};
    enc(tm, dt, 2, p, dims, strides, box, es,
        CU_TENSOR_MAP_INTERLEAVE_NONE, CU_TENSOR_MAP_SWIZZLE_128B,
        CU_TENSOR_MAP_L2_PROMOTION_L2_128B, CU_TENSOR_MAP_FLOAT_OOB_FILL_NONE);
}

extern "C" void kernel_launch(void* const* d_in, const int* in_sizes, int n_in,
                              void* d_out, int out_size)
{
    const float* x_emb = (const float*)d_in[0];
    const float* Wk = (const float*)d_in[2];
    const float* bk = (const float*)d_in[3];
    const float* Wq = (const float*)d_in[4];
    const float* bq = (const float*)d_in[5];
    const float* Wv = (const float*)d_in[6];
    const float* bv = (const float*)d_in[7];
    float* out = (float*)d_out;

    void* fp = nullptr;
    cudaDriverEntryPointQueryResult qst;
    cudaGetDriverEntryPointByVersion("cuTensorMapEncodeTiled", &fp, 12000, cudaEnableDefault, &qst);
    PFN_encode enc = (PFN_encode)fp;

    void *Xbh,*Xbl,*X32,*Wqh,*Wql,*Wkh,*Wkl,*Wv32,*Qbh,*Qbl,*Kbh,*Kbl,*Vth,*Sp,*Ph;
    cudaGetSymbolAddress(&Xbh, g_Xbh); cudaGetSymbolAddress(&Xbl, g_Xbl);
    cudaGetSymbolAddress(&X32, g_X32);
    cudaGetSymbolAddress(&Wqh, g_Wqh); cudaGetSymbolAddress(&Wql, g_Wql);
    cudaGetSymbolAddress(&Wkh, g_Wkh); cudaGetSymbolAddress(&Wkl, g_Wkl);
    cudaGetSymbolAddress(&Wv32, g_Wv32);
    cudaGetSymbolAddress(&Qbh, g_Qbh); cudaGetSymbolAddress(&Qbl, g_Qbl);
    cudaGetSymbolAddress(&Kbh, g_Kbh); cudaGetSymbolAddress(&Kbl, g_Kbl);
    cudaGetSymbolAddress(&Vth, g_Vth);
    cudaGetSymbolAddress(&Sp, g_S);    cudaGetSymbolAddress(&Ph, g_Ph);

    const CUtensorMapDataType BF = CU_TENSOR_MAP_DATA_TYPE_BFLOAT16;
    const CUtensorMapDataType F32 = CU_TENSOR_MAP_DATA_TYPE_FLOAT32;
    CUtensorMap tXh, tXl, tWqh, tWql, tWkh, tWkl;
    CUtensorMap tQh, tQl, tKh, tKl, tP, tV, tX32, tWv32;
    mk2d(enc, &tXh, Xbh, BF, E, MT, 64, 256, 2);
    mk2d(enc, &tXl, Xbl, BF, E, MT, 64, 256, 2);
    mk2d(enc, &tWqh, Wqh, BF, E, E, 64, 128, 2);
    mk2d(enc, &tWql, Wql, BF, E, E, 64, 128, 2);
    mk2d(enc, &tWkh, Wkh, BF, E, E, 64, 128, 2);
    mk2d(enc, &tWkl, Wkl, BF, E, E, 64, 128, 2);
    mk2d(enc, &tQh, Qbh, BF, E, MT, 64, 256, 2);
    mk2d(enc, &tQl, Qbl, BF, E, MT, 64, 256, 2);
    mk2d(enc, &tKh, Kbh, BF, E, MT, 64, 128, 2);
    mk2d(enc, &tKl, Kbl, BF, E, MT, 64, 128, 2);
    mk2d(enc, &tP, Ph, F32, T, (uint64_t)NB*T, 32, 256, 4);
    mk2d(enc, &tV, Vth, F32, T, (uint64_t)NB*E, 32, 128, 4);
    mk2d(enc, &tX32, X32, F32, E, MT, 32, 256, 4);
    mk2d(enc, &tWv32, Wv32, F32, E, E, 32, 128, 4);

    cudaFuncSetAttribute(gemm_bf16<0>, cudaFuncAttributeMaxDynamicSharedMemorySize, BSMEM_BYTES);
    cudaFuncSetAttribute(gemm_bf16<2>, cudaFuncAttributeMaxDynamicSharedMemorySize, BSMEM_BYTES);
    cudaFuncSetAttribute(gemm_tf32<0>, cudaFuncAttributeMaxDynamicSharedMemorySize, OSMEM_BYTES);
    cudaFuncSetAttribute(gemm_tf32<1>, cudaFuncAttributeMaxDynamicSharedMemorySize, OSMEM_BYTES);

    // 1. splits + tf32 roundings
    splitk_bf<<<(MT*E/4 + 255)/256, 256>>>(x_emb, (bf16*)Xbh, (bf16*)Xbl, (float*)X32, MT*E/4);
    splitk_bf<<<(E*E/4 + 255)/256, 256>>>(Wq, (bf16*)Wqh, (bf16*)Wql, nullptr, E*E/4);
    splitk_bf<<<(E*E/4 + 255)/256, 256>>>(Wk, (bf16*)Wkh, (bf16*)Wkl, nullptr, E*E/4);
    roundtf<<<(E*E/4 + 255)/256, 256>>>(Wv, (float*)Wv32, E*E/4);

    // 2. merged Q+K projection + V projection
    dim3 gqk(E/128, MT/256, 2);
    gemm_bf16<0><<<gqk, 544, BSMEM_BYTES>>>(tXh, tXl, tWqh, tWql, tWkh, tWkl,
                                            nullptr,
                                            (bf16*)Qbh, (bf16*)Qbl, (bf16*)Kbh, (bf16*)Kbl,
                                            bq, bk);
    dim3 gp(E/128, MT/256);
    gemm_tf32<1><<<gp, 544, OSMEM_BYTES>>>(tX32, tWv32, (float*)Vth, bv);

    // 3. scores (lower triangle at 256-row bands)
    dim3 gs(T/128, T/256, NB);
    gemm_bf16<2><<<gs, 544, BSMEM_BYTES>>>(tQh, tQl, tKh, tKl, tKh, tKl,
                                           (float*)Sp,
                                           nullptr, nullptr, nullptr, nullptr,
                                           nullptr, nullptr);

    // 4. fused column softmax (single exp) + fold 1/L into V
    dim3 gsc(T/32, NB);
    softcol<<<gsc, 256>>>();
    vscale<<<((size_t)NB*E*T/4 + 255)/256, 256>>>((int)((size_t)NB*E*T/4));

    // 5. output gemm (A = expS, B = V*linv; longest bands first)
    dim3 go(E/128, T/256, NB);
    gemm_tf32<0><<<go, 544, OSMEM_BYTES>>>(tP, tV, out, nullptr);
}

// round 16
// speedup vs baseline: 1.0138x; 1.0138x over previous
#include <cuda_runtime.h>
#include <cuda.h>
#include <cuda_bf16.h>
#include <math.h>
#include <stdint.h>

#define NB 8
#define T  2048
#define E  1024
#define MT (NB*T)

typedef __nv_bfloat16 bf16;

// ------------------------- scratch (device globals) -------------------------
__device__ bf16 g_Xbh[(size_t)MT*E], g_Xbl[(size_t)MT*E];
__device__ float g_X32[(size_t)MT*E];            // tf32-rna-rounded X
__device__ bf16 g_Wqh[(size_t)E*E], g_Wql[(size_t)E*E];
__device__ bf16 g_Wkh[(size_t)E*E], g_Wkl[(size_t)E*E];
__device__ float g_Wv32[(size_t)E*E];            // tf32-rna-rounded Wv
__device__ bf16 g_Qbh[(size_t)MT*E], g_Qbl[(size_t)MT*E];
__device__ bf16 g_Kbh[(size_t)MT*E], g_Kbl[(size_t)MT*E];
__device__ float g_Vth[(size_t)NB*E*T];          // [b][f][t], tf32-rounded
__device__ float g_S [(size_t)NB*T*T];
__device__ float g_Ph[(size_t)NB*T*T];
__device__ float g_M[NB*T], g_Li[NB*T];

// ------------------------- helpers -------------------------
__device__ __forceinline__ uint32_t smem_u32(const void* p) {
    uint32_t a;
    asm("{ .reg .u64 t; cvta.to.shared.u64 t, %1; cvt.u32.u64 %0, t; }" : "=r"(a) : "l"(p));
    return a;
}
__device__ __forceinline__ float tf32_rna(float x) {
    uint32_t u; asm("cvt.rna.tf32.f32 %0, %1;" : "=r"(u) : "f"(x));
    return __uint_as_float(u);
}
__device__ __forceinline__ void tma2d(uint32_t dst, const void* map, int x, int y, uint32_t mbar) {
    asm volatile("cp.async.bulk.tensor.2d.shared::cta.global.tile.mbarrier::complete_tx::bytes "
                 "[%0], [%1, {%2, %3}], [%4];"
                 :: "r"(dst), "l"(map), "r"(x), "r"(y), "r"(mbar) : "memory");
}
#define MBAR_INIT(a, c) \
    asm volatile("mbarrier.init.shared.b64 [%0], %1;" :: "r"((uint32_t)(a)), "r"((uint32_t)(c)) : "memory")
#define MBAR_EXPECT(a, b) \
    asm volatile("mbarrier.arrive.expect_tx.shared.b64 _, [%0], %1;" :: "r"((uint32_t)(a)), "r"((uint32_t)(b)) : "memory")
#define MBAR_ARRIVE(a) \
    asm volatile("mbarrier.arrive.shared.b64 _, [%0];" :: "r"((uint32_t)(a)) : "memory")
#define MBAR_WAIT(a, ph) do { \
    uint32_t _m = (uint32_t)(a), _p = (uint32_t)(ph), _d; \
    asm volatile("{\n\t.reg .pred p;\n\t" \
        "mbarrier.try_wait.parity.acquire.cta.shared::cta.b64 p, [%1], %2;\n\t" \
        "selp.b32 %0,1,0,p;\n\t}" : "=r"(_d) : "r"(_m), "r"(_p) : "memory"); \
    if (!_d) { \
        asm volatile("{\n\t.reg .pred P1;\n\t" \
            "WL_%=:\n\t" \
            "mbarrier.try_wait.parity.acquire.cta.shared::cta.b64 P1, [%0], %1, 0x989680;\n\t" \
            "@P1 bra.uni WD_%=;\n\tbra.uni WL_%=;\n\tWD_%=:\n\t}" \
            :: "r"(_m), "r"(_p) : "memory"); \
    } \
} while(0)
__device__ __forceinline__ void ldsm4(uint32_t& r0, uint32_t& r1, uint32_t& r2, uint32_t& r3,
                                      uint32_t addr) {
    asm volatile("ldmatrix.sync.aligned.m8n8.x4.shared.b16 {%0,%1,%2,%3}, [%4];"
                 : "=r"(r0), "=r"(r1), "=r"(r2), "=r"(r3) : "r"(addr));
}
__device__ __forceinline__ void mma16(float* d, uint32_t a0, uint32_t a1, uint32_t a2, uint32_t a3,
                                      uint32_t b0, uint32_t b1) {
    asm("mma.sync.aligned.m16n8k16.row.col.f32.bf16.bf16.f32 "
        "{%0,%1,%2,%3},{%4,%5,%6,%7},{%8,%9},{%0,%1,%2,%3};"
        : "+f"(d[0]), "+f"(d[1]), "+f"(d[2]), "+f"(d[3])
        : "r"(a0), "r"(a1), "r"(a2), "r"(a3), "r"(b0), "r"(b1));
}
__device__ __forceinline__ void mma8(float* d, uint32_t a0, uint32_t a1, uint32_t a2, uint32_t a3,
                                     uint32_t b0, uint32_t b1) {
    asm("mma.sync.aligned.m16n8k8.row.col.f32.tf32.tf32.f32 "
        "{%0,%1,%2,%3},{%4,%5,%6,%7},{%8,%9},{%0,%1,%2,%3};"
        : "+f"(d[0]), "+f"(d[1]), "+f"(d[2]), "+f"(d[3])
        : "r"(a0), "r"(a1), "r"(a2), "r"(a3), "r"(b0), "r"(b1));
}
__device__ __forceinline__ uint32_t pack_bf2(float x, float y) {
    bf16 hx = __float2bfloat16(x), hy = __float2bfloat16(y);
    uint16_t ux = *(uint16_t*)&hx, uy = *(uint16_t*)&hy;
    uint32_t r;
    asm("mov.b32 %0, {%1, %2};" : "=r"(r) : "h"(ux), "h"(uy));
    return r;
}

#define BSTG 98304
#define OSTG 49152
#define PSMEM_BYTES 196608       // = 2*BSTG = 4*OSTG

// ============================================================
// Merged projection kernel: grid (8, 64, 3), 544 threads.
// z=0: Q proj (bf16 3-pass), z=1: K proj (bf16 3-pass),
// z=2: V proj (tf32 1-pass on rna-rounded X32/Wv32, transposed store).
// ============================================================
__global__ void __launch_bounds__(544, 1) proj_all(
    const __grid_constant__ CUtensorMap mXh, const __grid_constant__ CUtensorMap mXl,
    const __grid_constant__ CUtensorMap mWqh, const __grid_constant__ CUtensorMap mWql,
    const __grid_constant__ CUtensorMap mWkh, const __grid_constant__ CUtensorMap mWkl,
    const __grid_constant__ CUtensorMap mX32, const __grid_constant__ CUtensorMap mWv32,
    bf16* __restrict__ Qh, bf16* __restrict__ Ql,
    bf16* __restrict__ Kh, bf16* __restrict__ Kl,
    float* __restrict__ Vt,
    const float* __restrict__ bq, const float* __restrict__ bk,
    const float* __restrict__ bv)
{
    const int z = blockIdx.z;
    const int m0 = blockIdx.y * 256, n0 = blockIdx.x * 128;

    extern __shared__ __align__(1024) char smem[];
    __shared__ __align__(8) uint64_t fullb[4], emptyb[4];
    const uint32_t sb = smem_u32(smem);
    const int tid = threadIdx.x;
    const int lane = tid & 31, warp = tid >> 5;
    const int wm = warp >> 2, wn = warp & 3;
    const int g = lane >> 2, c = lane & 3;

    if (tid == 0) {
        #pragma unroll
        for (int s = 0; s < 4; s++) {
            MBAR_INIT(smem_u32(&fullb[s]), 1);
            MBAR_INIT(smem_u32(&emptyb[s]), 16);
        }
    }
    __syncthreads();

    const int lmat = lane >> 3, lrow = lane & 7;
    const int aBit = lmat >> 1, bBit = lmat & 1;
    uint32_t aRow[4], bRow[2];
    #pragma unroll
    for (int mi = 0; mi < 4; mi++)
        aRow[mi] = (uint32_t)((wm*64 + mi*16 + ((lmat & 1) << 3) + lrow) * 128);
    #pragma unroll
    for (int p = 0; p < 2; p++)
        bRow[p] = (uint32_t)((wn*32 + p*16 + ((lmat >> 1) << 3) + lrow) * 128);

    if (z < 2) {
        // ---------------- bf16 3-pass Q/K projection ----------------
        const CUtensorMap* pBh = z ? &mWkh : &mWqh;
        const CUtensorMap* pBl = z ? &mWkl : &mWql;
        const int nch = E/64;

        if (warp == 16) {
            if (lane == 0) {
                for (int ck = 0; ck < nch; ck++) {
                    const int st = ck & 1;
                    MBAR_WAIT(smem_u32(&emptyb[st]), 1 ^ ((ck >> 1) & 1));
                    uint32_t base = sb + st*BSTG;
                    uint32_t fb = smem_u32(&fullb[st]);
                    MBAR_EXPECT(fb, BSTG);
                    tma2d(base + 0,     &mXh, 64*ck, m0, fb);
                    tma2d(base + 32768, &mXl, 64*ck, m0, fb);
                    tma2d(base + 65536, pBh, 64*ck, n0, fb);
                    tma2d(base + 81920, pBl, 64*ck, n0, fb);
                }
            }
            return;
        }

        float acc[4][4][4];
        #pragma unroll
        for (int mi = 0; mi < 4; mi++)
            #pragma unroll
            for (int ni = 0; ni < 4; ni++)
                #pragma unroll
                for (int q = 0; q < 4; q++) acc[mi][ni][q] = 0.f;

        for (int ck = 0; ck < nch; ck++) {
            const int st = ck & 1;
            MBAR_WAIT(smem_u32(&fullb[st]), (ck >> 1) & 1);

            const uint32_t stb = sb + st*BSTG;
            const uint32_t Ah = stb, Al = stb + 32768, Bh = stb + 65536, Bl = stb + 81920;

            #pragma unroll
            for (int ks = 0; ks < 4; ks++) {
                const uint32_t aU = (uint32_t)(((2*ks + aBit) ^ lrow) << 4);
                const uint32_t bU = (uint32_t)(((2*ks + bBit) ^ lrow) << 4);
                uint32_t bh[4][2], bl[4][2];
                ldsm4(bh[0][0], bh[0][1], bh[1][0], bh[1][1], Bh + bRow[0] + bU);
                ldsm4(bh[2][0], bh[2][1], bh[3][0], bh[3][1], Bh + bRow[1] + bU);
                ldsm4(bl[0][0], bl[0][1], bl[1][0], bl[1][1], Bl + bRow[0] + bU);
                ldsm4(bl[2][0], bl[2][1], bl[3][0], bl[3][1], Bl + bRow[1] + bU);
                uint32_t af[4][4];
                #pragma unroll
                for (int mi = 0; mi < 4; mi++)
                    ldsm4(af[mi][0], af[mi][1], af[mi][2], af[mi][3], Ah + aRow[mi] + aU);
                #pragma unroll
                for (int mi = 0; mi < 4; mi++)
                    #pragma unroll
                    for (int ni = 0; ni < 4; ni++)
                        mma16(acc[mi][ni], af[mi][0], af[mi][1], af[mi][2], af[mi][3],
                              bh[ni][0], bh[ni][1]);
                #pragma unroll
                for (int mi = 0; mi < 4; mi++)
                    #pragma unroll
                    for (int ni = 0; ni < 4; ni++)
                        mma16(acc[mi][ni], af[mi][0], af[mi][1], af[mi][2], af[mi][3],
                              bl[ni][0], bl[ni][1]);
                #pragma unroll
                for (int mi = 0; mi < 4; mi++)
                    ldsm4(af[mi][0], af[mi][1], af[mi][2], af[mi][3], Al + aRow[mi] + aU);
                #pragma unroll
                for (int mi = 0; mi < 4; mi++)
                    #pragma unroll
                    for (int ni = 0; ni < 4; ni++)
                        mma16(acc[mi][ni], af[mi][0], af[mi][1], af[mi][2], af[mi][3],
                              bh[ni][0], bh[ni][1]);
            }
            if (lane == 0) MBAR_ARRIVE(smem_u32(&emptyb[st]));
        }

        bf16* oh = z ? Kh : Qh;
        bf16* ol = z ? Kl : Ql;
        const float* bias = z ? bk : bq;

        #pragma unroll
        for (int mi = 0; mi < 4; mi++) {
            #pragma unroll
            for (int ni = 0; ni < 4; ni++) {
                const int r1 = m0 + wm*64 + mi*16 + g, r2 = r1 + 8;
                const int col = n0 + wn*32 + ni*8 + 2*c;
                float* a = acc[mi][ni];
                float2 bs = *(const float2*)(bias + col);
                float y0 = a[0] + bs.x, y1 = a[1] + bs.y;
                float y2 = a[2] + bs.x, y3 = a[3] + bs.y;
                float h0 = __bfloat162float(__float2bfloat16(y0));
                float h1 = __bfloat162float(__float2bfloat16(y1));
                float h2 = __bfloat162float(__float2bfloat16(y2));
                float h3 = __bfloat162float(__float2bfloat16(y3));
                *(uint32_t*)(oh + (size_t)r1*E + col) = pack_bf2(y0, y1);
                *(uint32_t*)(ol + (size_t)r1*E + col) = pack_bf2(y0 - h0, y1 - h1);
                *(uint32_t*)(oh + (size_t)r2*E + col) = pack_bf2(y2, y3);
                *(uint32_t*)(ol + (size_t)r2*E + col) = pack_bf2(y2 - h2, y3 - h3);
            }
        }
    } else {
        // ---------------- tf32 1-pass V projection ----------------
        const int nch = E/32;

        if (warp == 16) {
            if (lane == 0) {
                for (int ck = 0; ck < nch; ck++) {
                    const int st = ck & 3;
                    MBAR_WAIT(smem_u32(&emptyb[st]), 1 ^ ((ck >> 2) & 1));
                    uint32_t base = sb + st*OSTG;
                    uint32_t fb = smem_u32(&fullb[st]);
                    MBAR_EXPECT(fb, OSTG);
                    tma2d(base + 0,     &mX32, 32*ck, m0, fb);
                    tma2d(base + 32768, &mWv32, 32*ck, n0, fb);
                }
            }
            return;
        }

        float acc[4][4][4];
        #pragma unroll
        for (int mi = 0; mi < 4; mi++)
            #pragma unroll
            for (int ni = 0; ni < 4; ni++)
                #pragma unroll
                for (int q = 0; q < 4; q++) acc[mi][ni][q] = 0.f;

        for (int ck = 0; ck < nch; ck++) {
            const int st = ck & 3;
            MBAR_WAIT(smem_u32(&fullb[st]), (ck >> 2) & 1);

            const uint32_t stb = sb + st*OSTG;
            const uint32_t Aa = stb, Bb = stb + 32768;

            #pragma unroll
            for (int ks = 0; ks < 4; ks++) {
                const uint32_t aU = (uint32_t)(((2*ks + aBit) ^ lrow) << 4);
                const uint32_t bU = (uint32_t)(((2*ks + bBit) ^ lrow) << 4);
                uint32_t bh[4][2];
                ldsm4(bh[0][0], bh[0][1], bh[1][0], bh[1][1], Bb + bRow[0] + bU);
                ldsm4(bh[2][0], bh[2][1], bh[3][0], bh[3][1], Bb + bRow[1] + bU);
                #pragma unroll
                for (int mi = 0; mi < 4; mi++) {
                    uint32_t a0, a1, a2, a3;
                    ldsm4(a0, a1, a2, a3, Aa + aRow[mi] + aU);
                    #pragma unroll
                    for (int ni = 0; ni < 4; ni++)
                        mma8(acc[mi][ni], a0, a1, a2, a3, bh[ni][0], bh[ni][1]);
                }
            }
            if (lane == 0) MBAR_ARRIVE(smem_u32(&emptyb[st]));
        }

        #pragma unroll
        for (int mi = 0; mi < 4; mi++) {
            #pragma unroll
            for (int ni = 0; ni < 4; ni++) {
                const int col = n0 + wn*32 + ni*8 + 2*c;
                float* a = acc[mi][ni];
                float2 bs = *(const float2*)(bv + col);
                const size_t bo = (size_t)(m0 / T) * E * T;
                const int tl1 = (m0 % T) + wm*64 + mi*16 + g, tl2 = tl1 + 8;
                Vt[bo + (size_t)col*T     + tl1] = tf32_rna(a[0] + bs.x);
                Vt[bo + (size_t)(col+1)*T + tl1] = tf32_rna(a[1] + bs.y);
                Vt[bo + (size_t)col*T     + tl2] = tf32_rna(a[2] + bs.x);
                Vt[bo + (size_t)(col+1)*T + tl2] = tf32_rna(a[3] + bs.y);
            }
        }
    }
}

// ============================================================
// scores: bf16 3-pass, TMA + ldmatrix + producer warp.
// grid (16, 8, NB), triangle; fp32 store to S.
// ============================================================
__global__ void __launch_bounds__(544, 1) gemm_scores(
    const __grid_constant__ CUtensorMap mAh, const __grid_constant__ CUtensorMap mAl,
    const __grid_constant__ CUtensorMap mBh, const __grid_constant__ CUtensorMap mBl,
    float* __restrict__ outf)
{
    const int m0 = blockIdx.y * 256, n0 = blockIdx.x * 128;
    if (n0 >= m0 + 256) return;

    extern __shared__ __align__(1024) char smem[];
    __shared__ __align__(8) uint64_t fullb[2], emptyb[2];
    const uint32_t sb = smem_u32(smem);
    const int tid = threadIdx.x;
    const int lane = tid & 31, warp = tid >> 5;
    const int wm = warp >> 2, wn = warp & 3;
    const int g = lane >> 2, c = lane & 3;
    const int z = blockIdx.z;

    const int rowA = z*T + m0;
    const int rowB = z*T + n0;
    const int nch = E/64;

    if (tid == 0) {
        MBAR_INIT(smem_u32(&fullb[0]), 1);  MBAR_INIT(smem_u32(&fullb[1]), 1);
        MBAR_INIT(smem_u32(&emptyb[0]), 16); MBAR_INIT(smem_u32(&emptyb[1]), 16);
    }
    __syncthreads();

    if (warp == 16) {
        if (lane == 0) {
            for (int ck = 0; ck < nch; ck++) {
                const int st = ck & 1;
                MBAR_WAIT(smem_u32(&emptyb[st]), 1 ^ ((ck >> 1) & 1));
                uint32_t base = sb + st*BSTG;
                uint32_t fb = smem_u32(&fullb[st]);
                MBAR_EXPECT(fb, BSTG);
                tma2d(base + 0,     &mAh, 64*ck, rowA, fb);
                tma2d(base + 32768, &mAl, 64*ck, rowA, fb);
                tma2d(base + 65536, &mBh, 64*ck, rowB, fb);
                tma2d(base + 81920, &mBl, 64*ck, rowB, fb);
            }
        }
        return;
    }

    float acc[4][4][4];
    #pragma unroll
    for (int mi = 0; mi < 4; mi++)
        #pragma unroll
        for (int ni = 0; ni < 4; ni++)
            #pragma unroll
            for (int q = 0; q < 4; q++) acc[mi][ni][q] = 0.f;

    const int lmat = lane >> 3, lrow = lane & 7;
    const int aBit = lmat >> 1, bBit = lmat & 1;
    uint32_t aRow[4], bRow[2];
    #pragma unroll
    for (int mi = 0; mi < 4; mi++)
        aRow[mi] = (uint32_t)((wm*64 + mi*16 + ((lmat & 1) << 3) + lrow) * 128);
    #pragma unroll
    for (int p = 0; p < 2; p++)
        bRow[p] = (uint32_t)((wn*32 + p*16 + ((lmat >> 1) << 3) + lrow) * 128);

    for (int ck = 0; ck < nch; ck++) {
        const int st = ck & 1;
        MBAR_WAIT(smem_u32(&fullb[st]), (ck >> 1) & 1);

        const uint32_t stb = sb + st*BSTG;
        const uint32_t Ah = stb, Al = stb + 32768, Bh = stb + 65536, Bl = stb + 81920;

        #pragma unroll
        for (int ks = 0; ks < 4; ks++) {
            const uint32_t aU = (uint32_t)(((2*ks + aBit) ^ lrow) << 4);
            const uint32_t bU = (uint32_t)(((2*ks + bBit) ^ lrow) << 4);
            uint32_t bh[4][2], bl[4][2];
            ldsm4(bh[0][0], bh[0][1], bh[1][0], bh[1][1], Bh + bRow[0] + bU);
            ldsm4(bh[2][0], bh[2][1], bh[3][0], bh[3][1], Bh + bRow[1] + bU);
            ldsm4(bl[0][0], bl[0][1], bl[1][0], bl[1][1], Bl + bRow[0] + bU);
            ldsm4(bl[2][0], bl[2][1], bl[3][0], bl[3][1], Bl + bRow[1] + bU);
            uint32_t af[4][4];
            #pragma unroll
            for (int mi = 0; mi < 4; mi++)
                ldsm4(af[mi][0], af[mi][1], af[mi][2], af[mi][3], Ah + aRow[mi] + aU);
            #pragma unroll
            for (int mi = 0; mi < 4; mi++)
                #pragma unroll
                for (int ni = 0; ni < 4; ni++)
                    mma16(acc[mi][ni], af[mi][0], af[mi][1], af[mi][2], af[mi][3],
                          bh[ni][0], bh[ni][1]);
            #pragma unroll
            for (int mi = 0; mi < 4; mi++)
                #pragma unroll
                for (int ni = 0; ni < 4; ni++)
                    mma16(acc[mi][ni], af[mi][0], af[mi][1], af[mi][2], af[mi][3],
                          bl[ni][0], bl[ni][1]);
            #pragma unroll
            for (int mi = 0; mi < 4; mi++)
                ldsm4(af[mi][0], af[mi][1], af[mi][2], af[mi][3], Al + aRow[mi] + aU);
            #pragma unroll
            for (int mi = 0; mi < 4; mi++)
                #pragma unroll
                for (int ni = 0; ni < 4; ni++)
                    mma16(acc[mi][ni], af[mi][0], af[mi][1], af[mi][2], af[mi][3],
                          bh[ni][0], bh[ni][1]);
        }
        if (lane == 0) MBAR_ARRIVE(smem_u32(&emptyb[st]));
    }

    float* Sb = outf + (size_t)z*T*T;
    #pragma unroll
    for (int mi = 0; mi < 4; mi++) {
        #pragma unroll
        for (int ni = 0; ni < 4; ni++) {
            const int r1 = m0 + wm*64 + mi*16 + g, r2 = r1 + 8;
            const int col = n0 + wn*32 + ni*8 + 2*c;
            float* a = acc[mi][ni];
            *(float2*)(Sb + (size_t)r1*T + col) = make_float2(a[0], a[1]);
            *(float2*)(Sb + (size_t)r2*T + col) = make_float2(a[2], a[3]);
        }
    }
}

// ============================================================
// out GEMM: tf32 1-pass, TMA + ldmatrix + producer, 256x128, BK=32,
// 4 stages; longest diagonal bands first.
// ============================================================
__global__ void __launch_bounds__(544, 1) gemm_out(
    const __grid_constant__ CUtensorMap mA, const __grid_constant__ CUtensorMap mB,
    float* __restrict__ out0)
{
    const int yb = gridDim.y - 1 - blockIdx.y;
    const int m0 = yb * 256, n0 = blockIdx.x * 128;
    extern __shared__ __align__(1024) char smem[];
    __shared__ __align__(8) uint64_t fullb[4], emptyb[4];
    const uint32_t sb = smem_u32(smem);
    const int tid = threadIdx.x;
    const int lane = tid & 31, warp = tid >> 5;
    const int wm = warp >> 2, wn = warp & 3;
    const int g = lane >> 2, c = lane & 3;
    const int b = blockIdx.z;

    const int rowA = b*T + m0;
    const int rowB = b*E + n0;
    const int nch = m0/32 + 8;

    if (tid == 0) {
        #pragma unroll
        for (int s = 0; s < 4; s++) {
            MBAR_INIT(smem_u32(&fullb[s]), 1);
            MBAR_INIT(smem_u32(&emptyb[s]), 16);
        }
    }
    __syncthreads();

    if (warp == 16) {
        if (lane == 0) {
            for (int ck = 0; ck < nch; ck++) {
                const int st = ck & 3;
                MBAR_WAIT(smem_u32(&emptyb[st]), 1 ^ ((ck >> 2) & 1));
                uint32_t base = sb + st*OSTG;
                uint32_t fb = smem_u32(&fullb[st]);
                MBAR_EXPECT(fb, OSTG);
                tma2d(base + 0,     &mA, 32*ck, rowA, fb);
                tma2d(base + 32768, &mB, 32*ck, rowB, fb);
            }
        }
        return;
    }

    float acc[4][4][4];
    #pragma unroll
    for (int mi = 0; mi < 4; mi++)
        #pragma unroll
        for (int ni = 0; ni < 4; ni++)
            #pragma unroll
            for (int q = 0; q < 4; q++) acc[mi][ni][q] = 0.f;

    const int lmat = lane >> 3, lrow = lane & 7;
    const int aBit = lmat >> 1, bBit = lmat & 1;
    uint32_t aRow[4], bRow[2];
    #pragma unroll
    for (int mi = 0; mi < 4; mi++)
        aRow[mi] = (uint32_t)((wm*64 + mi*16 + ((lmat & 1) << 3) + lrow) * 128);
    #pragma unroll
    for (int p = 0; p < 2; p++)
        bRow[p] = (uint32_t)((wn*32 + p*16 + ((lmat >> 1) << 3) + lrow) * 128);

    for (int ck = 0; ck < nch; ck++) {
        const int st = ck & 3;
        MBAR_WAIT(smem_u32(&fullb[st]), (ck >> 2) & 1);

        const uint32_t stb = sb + st*OSTG;
        const uint32_t Aa = stb, Bb = stb + 32768;

        #pragma unroll
        for (int ks = 0; ks < 4; ks++) {
            const uint32_t aU = (uint32_t)(((2*ks + aBit) ^ lrow) << 4);
            const uint32_t bU = (uint32_t)(((2*ks + bBit) ^ lrow) << 4);
            uint32_t bh[4][2];
            ldsm4(bh[0][0], bh[0][1], bh[1][0], bh[1][1], Bb + bRow[0] + bU);
            ldsm4(bh[2][0], bh[2][1], bh[3][0], bh[3][1], Bb + bRow[1] + bU);
            #pragma unroll
            for (int mi = 0; mi < 4; mi++) {
                uint32_t a0, a1, a2, a3;
                ldsm4(a0, a1, a2, a3, Aa + aRow[mi] + aU);
                #pragma unroll
                for (int ni = 0; ni < 4; ni++)
                    mma8(acc[mi][ni], a0, a1, a2, a3, bh[ni][0], bh[ni][1]);
            }
        }
        if (lane == 0) MBAR_ARRIVE(smem_u32(&emptyb[st]));
    }

    float* Ob = out0 + (size_t)b*T*E;
    #pragma unroll
    for (int mi = 0; mi < 4; mi++) {
        #pragma unroll
        for (int ni = 0; ni < 4; ni++) {
            const int r1 = m0 + wm*64 + mi*16 + g, r2 = r1 + 8;
            const int col = n0 + wn*32 + ni*8 + 2*c;
            float* a = acc[mi][ni];
            *(float2*)(Ob + (size_t)r1*E + col) = make_float2(a[0], a[1]);
            *(float2*)(Ob + (size_t)r2*E + col) = make_float2(a[2], a[3]);
        }
    }
}

// ------------------------- elementwise kernels -------------------------
__global__ void __launch_bounds__(256) splitk_bf(
    const float* __restrict__ src, bf16* __restrict__ dh, bf16* __restrict__ dl,
    float* __restrict__ d32, int n4)
{
    int i = blockIdx.x * 256 + threadIdx.x;
    if (i >= n4) return;
    float4 v = ((const float4*)src)[i];
    uint32_t h0 = pack_bf2(v.x, v.y), h1 = pack_bf2(v.z, v.w);
    float r0 = v.x - __bfloat162float(__float2bfloat16(v.x));
    float r1 = v.y - __bfloat162float(__float2bfloat16(v.y));
    float r2 = v.z - __bfloat162float(__float2bfloat16(v.z));
    float r3 = v.w - __bfloat162float(__float2bfloat16(v.w));
    uint32_t l0 = pack_bf2(r0, r1), l1 = pack_bf2(r2, r3);
    ((uint2*)dh)[i] = make_uint2(h0, h1);
    ((uint2*)dl)[i] = make_uint2(l0, l1);
    if (d32) {
        float4 t;
        t.x = tf32_rna(v.x); t.y = tf32_rna(v.y);
        t.z = tf32_rna(v.z); t.w = tf32_rna(v.w);
        ((float4*)d32)[i] = t;
    }
}

__global__ void __launch_bounds__(256) roundtf(
    const float* __restrict__ src, float* __restrict__ dst, int n4)
{
    int i = blockIdx.x * 256 + threadIdx.x;
    if (i >= n4) return;
    float4 v = ((const float4*)src)[i];
    float4 t;
    t.x = tf32_rna(v.x); t.y = tf32_rna(v.y);
    t.z = tf32_rna(v.z); t.w = tf32_rna(v.w);
    ((float4*)dst)[i] = t;
}

// per-key-column j stats over i>=j (softmax over QUERY axis quirk), MLP=4
__global__ void __launch_bounds__(256) colstats()
{
    const int bb = blockIdx.y;
    const int j0 = blockIdx.x * 32;
    const int c = threadIdx.x & 31, r = threadIdx.x >> 5;
    const int j = j0 + c;
    const float* S = g_S + (size_t)bb*T*T;
    float m0v = -INFINITY, m1v = -INFINITY, m2v = -INFINITY, m3v = -INFINITY;
    float l0v = 0.f, l1v = 0.f, l2v = 0.f, l3v = 0.f;
    #define UPD(MM, LL, II) do { int _i = (II); if (_i >= j) { \
        float v = S[(size_t)_i*T + j]; \
        if (v <= MM) LL += __expf(v - MM); \
        else { LL = LL * __expf(MM - v) + 1.f; MM = v; } } } while(0)
    for (int i = j0 + r; i < T; i += 32) {
        UPD(m0v, l0v, i);
        UPD(m1v, l1v, i + 8);
        UPD(m2v, l2v, i + 16);
        UPD(m3v, l3v, i + 24);
    }
    #undef UPD
    float M = m0v, L = l0v;
    #define MRG(MM, LL) do { \
        if (MM > M) { L = L * __expf(M - MM) + LL; M = MM; } \
        else if (LL > 0.f) L += LL * __expf(MM - M); } while(0)
    MRG(m1v, l1v); MRG(m2v, l2v); MRG(m3v, l3v);
    __shared__ float sm_[8][33], sl_[8][33];
    sm_[r][c] = M; sl_[r][c] = L;
    __syncthreads();
    if (r == 0) {
        #pragma unroll
        for (int rr = 1; rr < 8; rr++) {
            float mm = sm_[rr][c], ll = sl_[rr][c];
            MRG(mm, ll);
        }
        g_M [bb*T + j] = M;
        g_Li[bb*T + j] = 1.f / L;
    }
    #undef MRG
}

__global__ void __launch_bounds__(256) psplit()
{
    const int jt = blockIdx.x, it = blockIdx.y;
    const int bb = blockIdx.z;
    const size_t base = (size_t)bb*T*T;
    const int i0 = it*128, j0 = jt*128;
    if (jt > it) {
        if (jt == it + 1 && (it & 1) == 0) {
            for (int idx = threadIdx.x; idx < 128*32; idx += 256) {
                int rr = idx >> 5, c4 = idx & 31;
                *(float4*)(g_Ph + base + (size_t)(i0+rr)*T + j0 + c4*4) =
                    make_float4(0.f, 0.f, 0.f, 0.f);
            }
        }
        return;
    }
    for (int idx = threadIdx.x; idx < 128*32; idx += 256) {
        int rr = idx >> 5, c4 = idx & 31;
        int i = i0 + rr, j = j0 + c4*4;
        float4 s = *(const float4*)(g_S + base + (size_t)i*T + j);
        float sv[4] = {s.x, s.y, s.z, s.w};
        float h[4];
        #pragma unroll
        for (int q = 0; q < 4; q++) {
            int jj = j + q;
            float p = (jj <= i) ? __expf(sv[q] - g_M[bb*T + jj]) * g_Li[bb*T + jj] : 0.f;
            h[q] = tf32_rna(p);
        }
        *(float4*)(g_Ph + base + (size_t)i*T + j) = make_float4(h[0], h[1], h[2], h[3]);
    }
}

// ------------------------- host -------------------------
typedef CUresult (*PFN_encode)(CUtensorMap*, CUtensorMapDataType, cuuint32_t, void*,
    const cuuint64_t*, const cuuint64_t*, const cuuint32_t*, const cuuint32_t*,
    CUtensorMapInterleave, CUtensorMapSwizzle, CUtensorMapL2promotion, CUtensorMapFloatOOBfill);

static void mk2d(PFN_encode enc, CUtensorMap* tm, void* p, CUtensorMapDataType dt,
                 uint64_t w, uint64_t h, uint32_t bw, uint32_t bh, uint32_t esize) {
    cuuint64_t dims[2]    = {w, h};
    cuuint64_t strides[1] = {w * esize};
    cuuint32_t box[2]     = {bw, bh};
    cuuint32_t es[2]      = {1, 1};
    enc(tm, dt, 2, p, dims, strides, box, es,
        CU_TENSOR_MAP_INTERLEAVE_NONE, CU_TENSOR_MAP_SWIZZLE_128B,
        CU_TENSOR_MAP_L2_PROMOTION_L2_128B, CU_TENSOR_MAP_FLOAT_OOB_FILL_NONE);
}

extern "C" void kernel_launch(void* const* d_in, const int* in_sizes, int n_in,
                              void* d_out, int out_size)
{
    const float* x_emb = (const float*)d_in[0];
    const float* Wk = (const float*)d_in[2];
    const float* bk = (const float*)d_in[3];
    const float* Wq = (const float*)d_in[4];
    const float* bq = (const float*)d_in[5];
    const float* Wv = (const float*)d_in[6];
    const float* bv = (const float*)d_in[7];
    float* out = (float*)d_out;

    void* fp = nullptr;
    cudaDriverEntryPointQueryResult qst;
    cudaGetDriverEntryPointByVersion("cuTensorMapEncodeTiled", &fp, 12000, cudaEnableDefault, &qst);
    PFN_encode enc = (PFN_encode)fp;

    void *Xbh,*Xbl,*X32,*Wqh,*Wql,*Wkh,*Wkl,*Wv32,*Qbh,*Qbl,*Kbh,*Kbl,*Vth,*Sp,*Ph;
    cudaGetSymbolAddress(&Xbh, g_Xbh); cudaGetSymbolAddress(&Xbl, g_Xbl);
    cudaGetSymbolAddress(&X32, g_X32);
    cudaGetSymbolAddress(&Wqh, g_Wqh); cudaGetSymbolAddress(&Wql, g_Wql);
    cudaGetSymbolAddress(&Wkh, g_Wkh); cudaGetSymbolAddress(&Wkl, g_Wkl);
    cudaGetSymbolAddress(&Wv32, g_Wv32);
    cudaGetSymbolAddress(&Qbh, g_Qbh); cudaGetSymbolAddress(&Qbl, g_Qbl);
    cudaGetSymbolAddress(&Kbh, g_Kbh); cudaGetSymbolAddress(&Kbl, g_Kbl);
    cudaGetSymbolAddress(&Vth, g_Vth);
    cudaGetSymbolAddress(&Sp, g_S);    cudaGetSymbolAddress(&Ph, g_Ph);

    const CUtensorMapDataType BF = CU_TENSOR_MAP_DATA_TYPE_BFLOAT16;
    const CUtensorMapDataType F32 = CU_TENSOR_MAP_DATA_TYPE_FLOAT32;
    CUtensorMap tXh, tXl, tWqh, tWql, tWkh, tWkl;
    CUtensorMap tQh, tQl, tKh, tKl, tP, tV, tX32, tWv32;
    mk2d(enc, &tXh, Xbh, BF, E, MT, 64, 256, 2);
    mk2d(enc, &tXl, Xbl, BF, E, MT, 64, 256, 2);
    mk2d(enc, &tWqh, Wqh, BF, E, E, 64, 128, 2);
    mk2d(enc, &tWql, Wql, BF, E, E, 64, 128, 2);
    mk2d(enc, &tWkh, Wkh, BF, E, E, 64, 128, 2);
    mk2d(enc, &tWkl, Wkl, BF, E, E, 64, 128, 2);
    mk2d(enc, &tQh, Qbh, BF, E, MT, 64, 256, 2);
    mk2d(enc, &tQl, Qbl, BF, E, MT, 64, 256, 2);
    mk2d(enc, &tKh, Kbh, BF, E, MT, 64, 128, 2);
    mk2d(enc, &tKl, Kbl, BF, E, MT, 64, 128, 2);
    mk2d(enc, &tP, Ph, F32, T, (uint64_t)NB*T, 32, 256, 4);
    mk2d(enc, &tV, Vth, F32, T, (uint64_t)NB*E, 32, 128, 4);
    mk2d(enc, &tX32, X32, F32, E, MT, 32, 256, 4);
    mk2d(enc, &tWv32, Wv32, F32, E, E, 32, 128, 4);

    cudaFuncSetAttribute(proj_all,    cudaFuncAttributeMaxDynamicSharedMemorySize, PSMEM_BYTES);
    cudaFuncSetAttribute(gemm_scores, cudaFuncAttributeMaxDynamicSharedMemorySize, PSMEM_BYTES);
    cudaFuncSetAttribute(gemm_out,    cudaFuncAttributeMaxDynamicSharedMemorySize, PSMEM_BYTES);

    // 1. splits + tf32 roundings
    splitk_bf<<<(MT*E/4 + 255)/256, 256>>>(x_emb, (bf16*)Xbh, (bf16*)Xbl, (float*)X32, MT*E/4);
    splitk_bf<<<(E*E/4 + 255)/256, 256>>>(Wq, (bf16*)Wqh, (bf16*)Wql, nullptr, E*E/4);
    splitk_bf<<<(E*E/4 + 255)/256, 256>>>(Wk, (bf16*)Wkh, (bf16*)Wkl, nullptr, E*E/4);
    roundtf<<<(E*E/4 + 255)/256, 256>>>(Wv, (float*)Wv32, E*E/4);

    // 2. merged Q+K+V projections in ONE launch (wave packing)
    dim3 gpj(E/128, MT/256, 3);
    proj_all<<<gpj, 544, PSMEM_BYTES>>>(tXh, tXl, tWqh, tWql, tWkh, tWkl, tX32, tWv32,
                                        (bf16*)Qbh, (bf16*)Qbl, (bf16*)Kbh, (bf16*)Kbl,
                                        (float*)Vth, bq, bk, bv);

    // 3. scores (lower triangle at 256-row bands)
    dim3 gs(T/128, T/256, NB);
    gemm_scores<<<gs, 544, PSMEM_BYTES>>>(tQh, tQl, tKh, tKl, (float*)Sp);

    // 4. column softmax stats + P build
    dim3 gc(T/32, NB);
    colstats<<<gc, 256>>>();
    psplit<<<dim3(T/128, T/128, NB), 256>>>();

    // 5. output gemm (longest bands first)
    dim3 go(E/128, T/256, NB);
    gemm_out<<<go, 544, PSMEM_BYTES>>>(tP, tV, out);
}